// round 1
// baseline (speedup 1.0000x reference)
#include <cuda_runtime.h>
#include <math.h>

// Problem constants
#define CCH 160
#define NT  110592          // 48*48*48
#define HWS 2304            // 48*48
#define WS  48

// conv_gemm (K1/K5) tiling: 160(M) x 128(N) x 32(K-chunk), 256 threads, 10x8 per thread
#define G_BN 128
#define G_TN 8
// shift_conv (K3) tiling: 160(M) x 64(N), 10x4 per thread (needs 2 accumulator sets)
#define S_BN 64
#define S_TN 4
#define BK   32
#define NTHREADS 256
#define TM   10

// Scratch (device globals; no allocation allowed)
__device__ float  g_h0[(size_t)CCH * NT];
__device__ float  g_y [(size_t)CCH * NT];
__device__ double g_stats[4];                       // sum1, sumsq1, sum2, sumsq2
__device__ float  g_alpha1[CCH], g_beta1[CCH];
__device__ float  g_alpha2[CCH], g_beta2[CCH];

__device__ __forceinline__ float gelu_erf(float t) {
    return 0.5f * t * (1.0f + erff(t * 0.70710678118654752f));
}

__global__ void zero_stats_kernel() {
    if (threadIdx.x < 4) g_stats[threadIdx.x] = 0.0;
}

// GroupNorm(1) finalize: scalar mean/var over all C*N elements -> per-channel affine
__global__ void finalize_kernel(int stage, const float* __restrict__ g,
                                const float* __restrict__ be) {
    __shared__ double sh[2];
    if (threadIdx.x == 0) {
        double Nd = (double)CCH * (double)NT;
        double m  = g_stats[stage * 2] / Nd;
        double v  = g_stats[stage * 2 + 1] / Nd - m * m;
        sh[0] = m;
        sh[1] = 1.0 / sqrt(v + 1e-5);
    }
    __syncthreads();
    const int c = threadIdx.x;   // launched with exactly CCH threads
    double mu = sh[0], rs = sh[1];
    float a = (float)((double)g[c] * rs);
    float b = (float)((double)be[c] - mu * (double)g[c] * rs);
    if (stage == 0) { g_alpha1[c] = a; g_beta1[c] = b; }
    else            { g_alpha2[c] = a; g_beta2[c] = b; }
}

// Block-level sum/sumsq reduction -> double atomics
__device__ __forceinline__ void stats_reduce(float lsum, float lsq, double* dst) {
    double s = (double)lsum, q = (double)lsq;
    #pragma unroll
    for (int o = 16; o > 0; o >>= 1) {
        s += __shfl_down_sync(0xffffffffu, s, o);
        q += __shfl_down_sync(0xffffffffu, q, o);
    }
    __shared__ double red[16];
    const int w = threadIdx.x >> 5, l = threadIdx.x & 31;
    if (l == 0) { red[w] = s; red[8 + w] = q; }
    __syncthreads();
    if (threadIdx.x == 0) {
        double S = 0.0, Q = 0.0;
        #pragma unroll
        for (int i = 0; i < 8; ++i) { S += red[i]; Q += red[8 + i]; }
        atomicAdd(&dst[0], S);
        atomicAdd(&dst[1], Q);
    }
}

// MODE 0: h0 = W@X + bias (X = input x), accumulate GN1 stats, write g_h0
// MODE 1: out = W@(alpha2*y+beta2) + bias, write Outp (d_out)
template<int MODE>
__global__ void __launch_bounds__(NTHREADS, 2) conv_gemm(
    const float* __restrict__ Wm, const float* __restrict__ Xp,
    const float* __restrict__ bias, float* __restrict__ Outp)
{
    __shared__ __align__(16) float As[BK][CCH + 1];
    __shared__ __align__(16) float Bs[BK][G_BN];
    const int t = threadIdx.x;
    const int tileN = blockIdx.x * G_BN;
    const int tx = t & 15, ty = t >> 4;
    const int lk = t & 31, lm0 = t >> 5;      // A-load: k lane, m base
    const int bn = t & (G_BN - 1), bk0 = t >> 7;  // B-load: n lane, k base {0,1}
    const float* X = (MODE == 0) ? Xp : g_y;
    float* Out = (MODE == 0) ? g_h0 : Outp;

    float acc[TM][G_TN];
    #pragma unroll
    for (int i = 0; i < TM; ++i)
        #pragma unroll
        for (int j = 0; j < G_TN; ++j) acc[i][j] = 0.f;

    for (int kc = 0; kc < 5; ++kc) {
        const int kb = kc * BK;
        #pragma unroll
        for (int i = 0; i < 20; ++i) {
            const int m = lm0 + i * 8;
            As[lk][m] = Wm[m * CCH + kb + lk];
        }
        #pragma unroll
        for (int i = 0; i < 16; ++i) {
            const int k = bk0 + i * 2;
            const int K = kb + k;
            float v = X[K * NT + tileN + bn];
            if (MODE == 1) v = fmaf(g_alpha2[K], v, g_beta2[K]);
            Bs[k][bn] = v;
        }
        __syncthreads();
        #pragma unroll
        for (int k = 0; k < BK; ++k) {
            float a[TM];
            #pragma unroll
            for (int i = 0; i < TM; ++i) a[i] = As[k][ty * TM + i];
            const float4 b0 = *reinterpret_cast<const float4*>(&Bs[k][tx * G_TN]);
            const float4 b1 = *reinterpret_cast<const float4*>(&Bs[k][tx * G_TN + 4]);
            const float b[G_TN] = {b0.x, b0.y, b0.z, b0.w, b1.x, b1.y, b1.z, b1.w};
            #pragma unroll
            for (int i = 0; i < TM; ++i)
                #pragma unroll
                for (int j = 0; j < G_TN; ++j)
                    acc[i][j] = fmaf(a[i], b[j], acc[i][j]);
        }
        __syncthreads();
    }

    float lsum = 0.f, lsq = 0.f;
    #pragma unroll
    for (int i = 0; i < TM; ++i) {
        const int m = ty * TM + i;
        const float bb = bias[m];
        float v[G_TN];
        #pragma unroll
        for (int j = 0; j < G_TN; ++j) {
            v[j] = acc[i][j] + bb;
            if (MODE == 0) { lsum += v[j]; lsq += v[j] * v[j]; }
        }
        const float4 o0 = {v[0], v[1], v[2], v[3]};
        const float4 o1 = {v[4], v[5], v[6], v[7]};
        *reinterpret_cast<float4*>(&Out[m * NT + tileN + tx * G_TN])     = o0;
        *reinterpret_cast<float4*>(&Out[m * NT + tileN + tx * G_TN + 4]) = o1;
    }
    if (MODE == 0) stats_reduce(lsum, lsq, &g_stats[0]);
}

// K3: y = sum over 3 branches of gelu(W_br @ shift_br(gelu(affine1(h0))) + b_br)
// shift: channel chunk kc (32 ch) shifted by s = kc-2 along branch axis, zero fill.
// Also accumulates GN2 stats of y.
__global__ void __launch_bounds__(NTHREADS, 2) shift_conv(
    const float* __restrict__ W0, const float* __restrict__ W1, const float* __restrict__ W2,
    const float* __restrict__ bb0, const float* __restrict__ bb1, const float* __restrict__ bb2)
{
    __shared__ __align__(16) float As[BK][CCH + 1];
    __shared__ __align__(16) float Bs[BK][S_BN];
    const int t = threadIdx.x;
    const int tileN = blockIdx.x * S_BN;
    const int tx = t & 15, ty = t >> 4;
    const int lk = t & 31, lm0 = t >> 5;
    const int bn = t & (S_BN - 1), bk0 = t >> 6;  // bk0 in [0,4)

    // geometry for this thread's B-load column (fixed for whole kernel)
    const int n_g = tileN + bn;
    const int d_i = n_g / HWS;
    const int h_i = (n_g / WS) % WS;
    const int w_i = n_g % WS;

    float yv[TM][S_TN];
    #pragma unroll
    for (int i = 0; i < TM; ++i)
        #pragma unroll
        for (int j = 0; j < S_TN; ++j) yv[i][j] = 0.f;

    #pragma unroll 1
    for (int br = 0; br < 3; ++br) {
        const float* Wm   = (br == 0) ? W0  : ((br == 1) ? W1  : W2);
        const float* bias = (br == 0) ? bb0 : ((br == 1) ? bb1 : bb2);
        const int idx     = (br == 0) ? d_i : ((br == 1) ? h_i : w_i);
        const int stride  = (br == 0) ? HWS : ((br == 1) ? WS  : 1);

        float acc[TM][S_TN];
        #pragma unroll
        for (int i = 0; i < TM; ++i)
            #pragma unroll
            for (int j = 0; j < S_TN; ++j) acc[i][j] = 0.f;

        #pragma unroll 1
        for (int kc = 0; kc < 5; ++kc) {
            const int kb = kc * BK;
            const int s  = kc - 2;
            #pragma unroll
            for (int i = 0; i < 20; ++i) {
                const int m = lm0 + i * 8;
                As[lk][m] = Wm[m * CCH + kb + lk];
            }
            const bool valid = (unsigned)(idx - s) < (unsigned)WS;
            const int  src   = n_g - s * stride;
            #pragma unroll
            for (int i = 0; i < 8; ++i) {
                const int k = bk0 + i * 4;
                const int K = kb + k;
                float v = 0.f;
                if (valid)
                    v = gelu_erf(fmaf(g_alpha1[K], g_h0[K * NT + src], g_beta1[K]));
                Bs[k][bn] = v;
            }
            __syncthreads();
            #pragma unroll
            for (int k = 0; k < BK; ++k) {
                float a[TM];
                #pragma unroll
                for (int i = 0; i < TM; ++i) a[i] = As[k][ty * TM + i];
                const float4 b4 = *reinterpret_cast<const float4*>(&Bs[k][tx * S_TN]);
                const float b[S_TN] = {b4.x, b4.y, b4.z, b4.w};
                #pragma unroll
                for (int i = 0; i < TM; ++i)
                    #pragma unroll
                    for (int j = 0; j < S_TN; ++j)
                        acc[i][j] = fmaf(a[i], b[j], acc[i][j]);
            }
            __syncthreads();
        }
        #pragma unroll
        for (int i = 0; i < TM; ++i) {
            const float bb = bias[ty * TM + i];
            #pragma unroll
            for (int j = 0; j < S_TN; ++j)
                yv[i][j] += gelu_erf(acc[i][j] + bb);
        }
    }

    float lsum = 0.f, lsq = 0.f;
    #pragma unroll
    for (int i = 0; i < TM; ++i) {
        const int m = ty * TM + i;
        const float4 o = {yv[i][0], yv[i][1], yv[i][2], yv[i][3]};
        *reinterpret_cast<float4*>(&g_y[m * NT + tileN + tx * S_TN]) = o;
        #pragma unroll
        for (int j = 0; j < S_TN; ++j) { lsum += yv[i][j]; lsq += yv[i][j] * yv[i][j]; }
    }
    stats_reduce(lsum, lsq, &g_stats[2]);
}

extern "C" void kernel_launch(void* const* d_in, const int* in_sizes, int n_in,
                              void* d_out, int out_size) {
    const float* x   = (const float*)d_in[0];
    const float* w1  = (const float*)d_in[1];
    const float* b1  = (const float*)d_in[2];
    const float* g1  = (const float*)d_in[3];
    const float* be1 = (const float*)d_in[4];
    const float* w21 = (const float*)d_in[5];
    const float* b21 = (const float*)d_in[6];
    const float* w22 = (const float*)d_in[7];
    const float* b22 = (const float*)d_in[8];
    const float* w23 = (const float*)d_in[9];
    const float* b23 = (const float*)d_in[10];
    const float* g2  = (const float*)d_in[11];
    const float* be2 = (const float*)d_in[12];
    const float* w3  = (const float*)d_in[13];
    const float* b3  = (const float*)d_in[14];
    float* out = (float*)d_out;

    zero_stats_kernel<<<1, 32>>>();
    conv_gemm<0><<<NT / G_BN, NTHREADS>>>(w1, x, b1, nullptr);
    finalize_kernel<<<1, CCH>>>(0, g1, be1);
    shift_conv<<<NT / S_BN, NTHREADS>>>(w21, w22, w23, b21, b22, b23);
    finalize_kernel<<<1, CCH>>>(1, g2, be2);
    conv_gemm<1><<<NT / G_BN, NTHREADS>>>(w3, nullptr, b3, out);
}